// round 9
// baseline (speedup 1.0000x reference)
#include <cuda_runtime.h>
#include <cuda_bf16.h>

// MorletTransform via per-harmonic Goertzel recurrence (f32x2 packed lanes).
// Mapping: 256 threads/frame. Thread: quad = tid&15 -> harmonics 4q+1..4q+4
// as TWO f32x2 chains (ILP=2); segment = tid>>4 -> samples [seg*64, seg*64+64).
// Loop body: 1 LDS.128 (2 duplicated samples) + 8 FFMA2 (identical to R8).
// R9 restructure: GMEM loads issued first, coeff sincos overlapped with the
// audio load, separate sPart (no overlay barrier), single-warp tail.
// Barriers: 2 total.

#define TWO_PI_F 6.28318530717958647692f

__device__ __forceinline__ unsigned long long fma2(unsigned long long a,
                                                   unsigned long long b,
                                                   unsigned long long c) {
    unsigned long long d;
    asm("fma.rn.f32x2 %0, %1, %2, %3;" : "=l"(d) : "l"(a), "l"(b), "l"(c));
    return d;
}
__device__ __forceinline__ unsigned long long pk(float lo, float hi) {
    unsigned long long d;
    asm("mov.b64 %0, {%1, %2};" : "=l"(d) : "f"(lo), "f"(hi));
    return d;
}
__device__ __forceinline__ void upk(unsigned long long v, float& lo, float& hi) {
    asm("mov.b64 {%0, %1}, %2;" : "=f"(lo), "=f"(hi) : "l"(v));
}

__global__ void __launch_bounds__(256)
morlet_kernel(const float* __restrict__ audio,
              const float* __restrict__ f0,
              float* __restrict__ out_hd,
              float* __restrict__ out_amp) {
    const int f   = blockIdx.x;
    const int tid = threadIdx.x;

    __shared__ __align__(16) unsigned long long w2[1024];   // (w[n],w[n]); 8KB
    __shared__ __align__(16) float2 sPart[16 * 64];         // [seg][harmonic]; 8KB
    __shared__ __align__(8) float sCth[64];
    __shared__ __align__(8) float sSth[64];

    // normalizer = 1/sqrt(pi*tp), tp = sr/half_bw = 16000
    const float normalizer = rsqrtf(3.14159265358979f * 16000.0f);
    const float inv_tp     = 1.0f / 16000.0f;
    const float inv_sr     = 1.0f / 16000.0f;

    // --- issue both GMEM loads up front (independent, in flight together) ---
    float4 a = ((const float4*)audio)[(size_t)f * 256 + tid];
    const float f0v = f0[f];

    // --- per-harmonic recurrence coefficients: depends only on f0, so this
    //     overlaps the audio load. Accurate sincosf: cos error is amplified
    //     by 1/sin(theta) ~51 at k=1 -> __sincosf unsafe here. ---
    if (tid < 64) {
        float fc = f0v * (float)(tid + 1) * inv_sr;
        float s, c;
        sincosf(TWO_PI_F * fc, &s, &c);
        sCth[tid] = c;
        sSth[tid] = s;
    }

    // --- windowed frame: thread handles samples 4*tid .. 4*tid+3 ---
    {
        int n = tid * 4;
        float v[4] = {a.x, a.y, a.z, a.w};
        unsigned long long o[4];
        #pragma unroll
        for (int i = 0; i < 4; ++i) {
            float d  = (float)(n + i - 512);
            float wv = v[i] * (normalizer * __expf(-d * d * inv_tp));
            o[i] = pk(wv, wv);
        }
        ((ulonglong2*)w2)[tid * 2]     = make_ulonglong2(o[0], o[1]);
        ((ulonglong2*)w2)[tid * 2 + 1] = make_ulonglong2(o[2], o[3]);
    }
    __syncthreads();   // barrier #1: w2 + coefficients ready

    const int quad = tid & 15;   // harmonics 4q+1 .. 4q+4
    const int seg  = tid >> 4;   // 16 segments of 64 samples

    float2 cthP = ((const float2*)sCth)[2 * quad];       // harmonics 4q+1, 4q+2
    float2 sthP = ((const float2*)sSth)[2 * quad];
    float2 cthQ = ((const float2*)sCth)[2 * quad + 1];   // harmonics 4q+3, 4q+4
    float2 sthQ = ((const float2*)sSth)[2 * quad + 1];
    const unsigned long long C2P  = pk(2.0f * cthP.x, 2.0f * cthP.y);
    const unsigned long long C2Q  = pk(2.0f * cthQ.x, 2.0f * cthQ.y);
    const unsigned long long NEG1 = pk(-1.0f, -1.0f);

    // --- Goertzel: two f32x2 chains over this thread's 64-sample segment ---
    const ulonglong2* wq = (const ulonglong2*)(w2 + seg * 64);

    unsigned long long p1 = 0ull, p2 = 0ull;  // chain P (harmonics 4q+1,4q+2)
    unsigned long long q1 = 0ull, q2 = 0ull;  // chain Q (harmonics 4q+3,4q+4)
    #pragma unroll
    for (int m = 0; m < 32; ++m) {
        ulonglong2 wv = wq[m];                         // 2 samples, duplicated
        unsigned long long t0 = fma2(NEG1, p2, wv.x);  // w - s_{n-2}
        unsigned long long s0 = fma2(C2P, p1, t0);
        unsigned long long u0 = fma2(NEG1, q2, wv.x);
        unsigned long long v0 = fma2(C2Q, q1, u0);
        unsigned long long t1 = fma2(NEG1, p1, wv.y);
        unsigned long long sn = fma2(C2P, s0, t1);
        unsigned long long u1 = fma2(NEG1, q1, wv.y);
        unsigned long long vn = fma2(C2Q, v0, u1);
        p2 = s0; p1 = sn;
        q2 = v0; q1 = vn;
    }

    // --- finalize 4 harmonics into the global frame ---
    const float nend = (float)(seg * 64 + 63);
    float re[4], im[4];
    {
        float x1A, x1B, x2A, x2B;
        upk(p1, x1A, x1B); upk(p2, x2A, x2B);
        float fcA = f0v * (float)(4 * quad + 1) * inv_sr;
        float fcB = f0v * (float)(4 * quad + 2) * inv_sr;
        float yre = fmaf(-cthP.x, x2A, x1A), yim = sthP.x * x2A;
        float p = fcA * nend; p -= floorf(p);
        float sphi, cphi; __sincosf(TWO_PI_F * p, &sphi, &cphi);
        re[0] = yre * cphi + yim * sphi; im[0] = yim * cphi - yre * sphi;
        yre = fmaf(-cthP.y, x2B, x1B); yim = sthP.y * x2B;
        p = fcB * nend; p -= floorf(p);
        __sincosf(TWO_PI_F * p, &sphi, &cphi);
        re[1] = yre * cphi + yim * sphi; im[1] = yim * cphi - yre * sphi;
    }
    {
        float x1A, x1B, x2A, x2B;
        upk(q1, x1A, x1B); upk(q2, x2A, x2B);
        float fcA = f0v * (float)(4 * quad + 3) * inv_sr;
        float fcB = f0v * (float)(4 * quad + 4) * inv_sr;
        float yre = fmaf(-cthQ.x, x2A, x1A), yim = sthQ.x * x2A;
        float p = fcA * nend; p -= floorf(p);
        float sphi, cphi; __sincosf(TWO_PI_F * p, &sphi, &cphi);
        re[2] = yre * cphi + yim * sphi; im[2] = yim * cphi - yre * sphi;
        yre = fmaf(-cthQ.y, x2B, x1B); yim = sthQ.y * x2B;
        p = fcB * nend; p -= floorf(p);
        __sincosf(TWO_PI_F * p, &sphi, &cphi);
        re[3] = yre * cphi + yim * sphi; im[3] = yim * cphi - yre * sphi;
    }

    // --- store partials (separate array; no overlay barrier needed) ---
    #pragma unroll
    for (int i = 0; i < 4; ++i)
        sPart[seg * 64 + 4 * quad + i] = make_float2(re[i], im[i]);
    __syncthreads();   // barrier #2: partials visible

    // --- single-warp finish: lane l owns harmonics 2l+1, 2l+2 ---
    if (tid < 32) {
        float r0 = 0.0f, i0 = 0.0f, r1 = 0.0f, i1 = 0.0f;
        #pragma unroll
        for (int s = 0; s < 16; ++s) {
            // one LDS.128: both harmonics' (re,im) for this segment
            float4 pq = *(const float4*)&sPart[s * 64 + 2 * tid];
            r0 += pq.x; i0 += pq.y;
            r1 += pq.z; i1 += pq.w;
        }
        float mag0 = sqrtf(r0 * r0 + i0 * i0);
        float mag1 = sqrtf(r1 * r1 + i1 * i1);
        float fch0 = f0v * (float)(2 * tid + 1) * inv_sr;
        float fch1 = f0v * (float)(2 * tid + 2) * inv_sr;
        if (fch0 > 0.5f) mag0 = 0.0f;   // Nyquist mask
        if (fch1 > 0.5f) mag1 = 0.0f;

        float s = mag0 + mag1;
        #pragma unroll
        for (int o = 16; o > 0; o >>= 1)
            s += __shfl_xor_sync(0xffffffffu, s, o);   // amp in all lanes

        float inv = 1.0f / s;
        ((float2*)out_hd)[f * 32 + tid] = make_float2(mag0 * inv, mag1 * inv);
        if (tid == 0)
            out_amp[f] = fminf(fmaxf(s * 2.0f, 0.0f), 1.0f);
    }
}

extern "C" void kernel_launch(void* const* d_in, const int* in_sizes, int n_in,
                              void* d_out, int out_size) {
    const float* audio = (const float*)d_in[0];
    const float* f0    = (const float*)d_in[1];
    const int frames   = in_sizes[1];  // 2*250*1 = 500
    float* out         = (float*)d_out;
    morlet_kernel<<<frames, 256>>>(audio, f0, out, out + (size_t)frames * 64);
}